// round 14
// baseline (speedup 1.0000x reference)
#include <cuda_runtime.h>
#include <math.h>

#define NN 50000
#define EE 800000

typedef unsigned long long ull;

__device__ __forceinline__ ull pack2(float lo, float hi) {
    ull r;
    asm("mov.b64 %0, {%1,%2};" : "=l"(r) : "f"(lo), "f"(hi));
    return r;
}
__device__ __forceinline__ float2 unpack2(ull v) {
    float2 r;
    asm("mov.b64 {%0,%1}, %2;" : "=f"(r.x), "=f"(r.y) : "l"(v));
    return r;
}
__device__ __forceinline__ void ffma2(ull& acc, ull a, ull b) {
    asm("fma.rn.f32x2 %0, %1, %2, %3;" : "=l"(acc) : "l"(a), "l"(b), "l"(acc));
}

// ---------------- scratch (device globals; no allocation) ----------------
__device__ float g_h1[NN * 128];     // h1 = x@W1 (pre-aggregation)
__device__ float g_as1[NN * 4];
__device__ float g_ad1[NN * 4];
__device__ float g_o1[NN * 128];     // ELU(aggregated layer-1 output)
__device__ float g_h2[NN * 64];      // h2 = o1@W2 (pre-aggregation)
__device__ float g_as2[NN];
__device__ float g_ad2[NN];
__device__ float g_o2[NN * 64];      // ELU(aggregated layer-2 output)
__device__ int   g_deg[NN];
__device__ int   g_cnt[NN];
__device__ int   g_rowp[NN + 1];
__device__ int   g_col[EE];

// ---------------- CSR build ----------------
__global__ void k_deg(const int* __restrict__ ei, int e) {
    int i = blockIdx.x * blockDim.x + threadIdx.x;
    if (i < e) atomicAdd(&g_deg[ei[e + i]], 1);
}

// one block, 1024 threads: serial chunk sums + block scan + serial writeback
__global__ void k_scan(int n) {
    __shared__ int part[1024];
    int tid = threadIdx.x;
    int C = (n + 1023) / 1024;
    int base = tid * C;
    int sum = 0;
    for (int i = 0; i < C; i++) {
        int idx = base + i;
        if (idx < n) sum += g_deg[idx];
    }
    part[tid] = sum;
    __syncthreads();
    for (int off = 1; off < 1024; off <<= 1) {
        int t = (tid >= off) ? part[tid - off] : 0;
        __syncthreads();
        part[tid] += t;
        __syncthreads();
    }
    int run = part[tid] - sum;   // exclusive
    for (int i = 0; i < C; i++) {
        int idx = base + i;
        if (idx < n) {
            g_rowp[idx] = run;
            run += g_deg[idx];
        }
    }
    if (tid == 1023) g_rowp[n] = part[1023];
}

__global__ void k_fill(const int* __restrict__ ei, int e) {
    int i = blockIdx.x * blockDim.x + threadIdx.x;
    if (i < e) {
        int src = ei[i];
        int dst = ei[e + i];
        int pos = g_rowp[dst] + atomicAdd(&g_cnt[dst], 1);
        g_col[pos] = src;
    }
}

// ---------------- layer 1 GEMM: h1 = x @ W1, alpha reductions ----------------
// 256 threads = 8 warps; each warp owns an 8-node tile, 4 cols per lane.
__global__ void __launch_bounds__(256) k_gemm1(
        const float* __restrict__ x, const float* __restrict__ W,
        const float* __restrict__ a_src, const float* __restrict__ a_dst,
        int n) {
    __shared__ float4 xs[64][32];
    int tid = threadIdx.x;
    int warp = tid >> 5;                // warp = 8-node tile
    int t = tid & 31;                   // lane = column group (cols 4t..4t+3)
    int blkbase = blockIdx.x * 64;

    for (int i = tid; i < 64 * 32; i += 256) {
        int m = i >> 5, k4 = i & 31;
        int node = blkbase + m;
        xs[m][k4] = (node < n) ? ((const float4*)x)[node * 32 + k4]
                               : make_float4(0.f, 0.f, 0.f, 0.f);
    }
    __syncthreads();

    ull accA[8], accB[8];               // (4t,4t+1) and (4t+2,4t+3)
#pragma unroll
    for (int m = 0; m < 8; m++) { accA[m] = 0ull; accB[m] = 0ull; }

#pragma unroll 2
    for (int k4 = 0; k4 < 32; k4++) {
        ull wpA[4], wpB[4];
#pragma unroll
        for (int kk = 0; kk < 4; kk++) {
            float4 wv = ((const float4*)W)[(k4 * 4 + kk) * 32 + t];
            wpA[kk] = pack2(wv.x, wv.y);
            wpB[kk] = pack2(wv.z, wv.w);
        }
#pragma unroll
        for (int m = 0; m < 8; m++) {
            float4 xv = xs[warp * 8 + m][k4];
            ull xx = pack2(xv.x, xv.x);
            ffma2(accA[m], xx, wpA[0]); ffma2(accB[m], xx, wpB[0]);
            xx = pack2(xv.y, xv.y);
            ffma2(accA[m], xx, wpA[1]); ffma2(accB[m], xx, wpB[1]);
            xx = pack2(xv.z, xv.z);
            ffma2(accA[m], xx, wpA[2]); ffma2(accB[m], xx, wpB[2]);
            xx = pack2(xv.w, xv.w);
            ffma2(accA[m], xx, wpA[3]); ffma2(accB[m], xx, wpB[3]);
        }
    }

    int head = t >> 3;                  // cols 4t..4t+3 lie within head t/8
    float4 av = ((const float4*)a_src)[t];
    float4 dv = ((const float4*)a_dst)[t];
#pragma unroll
    for (int m = 0; m < 8; m++) {
        int node = blkbase + warp * 8 + m;
        if (node >= n) break;
        float2 pa = unpack2(accA[m]);
        float2 pb = unpack2(accB[m]);
        float4 o = make_float4(pa.x, pa.y, pb.x, pb.y);
        *(float4*)&g_h1[node * 128 + t * 4] = o;
        float s = o.x * av.x + o.y * av.y + o.z * av.z + o.w * av.w;
        float d = o.x * dv.x + o.y * dv.y + o.z * dv.z + o.w * dv.w;
#pragma unroll
        for (int off = 4; off; off >>= 1) {
            s += __shfl_xor_sync(0xffffffffu, s, off);
            d += __shfl_xor_sync(0xffffffffu, d, off);
        }
        if ((t & 7) == 0) {
            g_as1[node * 4 + head] = s;
            g_ad1[node * 4 + head] = d;
        }
    }
}

// ---------------- layer 1 aggregation (gather, warp per node) ----------------
// batched col loads (one coalesced LDG per 32 edges), single accumulator.
__global__ void k_agg1(const float* __restrict__ b1, int n) {
    int node = (int)((blockIdx.x * (unsigned)blockDim.x + threadIdx.x) >> 5);
    int lane = threadIdx.x & 31;
    if (node >= n) return;
    int head = lane >> 3;

    float ad = __ldg(&g_ad1[node * 4 + head]);
    float v = __ldg(&g_as1[node * 4 + head]) + ad;   // self loop
    float w = __expf(v > 0.f ? v : 0.2f * v);
    float den = w;
    float4 hv = *(const float4*)&g_h1[node * 128 + lane * 4];
    float4 acc = make_float4(hv.x * w, hv.y * w, hv.z * w, hv.w * w);

    int rs = g_rowp[node], re = g_rowp[node + 1];
    for (int jb = rs; jb < re; jb += 32) {
        int cnt = re - jb; if (cnt > 32) cnt = 32;
        int cl = (jb + lane < re) ? __ldg(&g_col[jb + lane]) : 0;
        for (int u = 0; u < cnt; u++) {
            int src = __shfl_sync(0xffffffffu, cl, u);
            float vv = __ldg(&g_as1[src * 4 + head]) + ad;
            float ww = __expf(vv > 0.f ? vv : 0.2f * vv);
            den += ww;
            float4 h = *(const float4*)&g_h1[src * 128 + lane * 4];
            acc.x += h.x * ww;
            acc.y += h.y * ww;
            acc.z += h.z * ww;
            acc.w += h.w * ww;
        }
    }

    float inv = 1.f / (den + 1e-16f);
    float4 b = ((const float4*)b1)[lane];
    float4 o;
    o.x = acc.x * inv + b.x;
    o.y = acc.y * inv + b.y;
    o.z = acc.z * inv + b.z;
    o.w = acc.w * inv + b.w;
    o.x = o.x > 0.f ? o.x : expm1f(o.x);
    o.y = o.y > 0.f ? o.y : expm1f(o.y);
    o.z = o.z > 0.f ? o.z : expm1f(o.z);
    o.w = o.w > 0.f ? o.w : expm1f(o.w);
    *(float4*)&g_o1[node * 128 + lane * 4] = o;
}

// ---------------- layer 2 GEMM: h2 = o1 @ W2, scalar alphas ----------------
// 256 threads = 8 warps; each warp owns an 8-node tile, 2 cols per lane.
__global__ void __launch_bounds__(256) k_gemm2(
        const float* __restrict__ W, const float* __restrict__ a_src,
        const float* __restrict__ a_dst, int n) {
    __shared__ float4 xs[64][32];
    int tid = threadIdx.x;
    int warp = tid >> 5;
    int t = tid & 31;                   // cols 2t, 2t+1
    int blkbase = blockIdx.x * 64;

    for (int i = tid; i < 64 * 32; i += 256) {
        int m = i >> 5, k4 = i & 31;
        int node = blkbase + m;
        xs[m][k4] = (node < n) ? ((const float4*)g_o1)[node * 32 + k4]
                               : make_float4(0.f, 0.f, 0.f, 0.f);
    }
    __syncthreads();

    ull acc[8];
#pragma unroll
    for (int m = 0; m < 8; m++) acc[m] = 0ull;

#pragma unroll 2
    for (int k4 = 0; k4 < 32; k4++) {
        ull wp[4];
#pragma unroll
        for (int kk = 0; kk < 4; kk++) {
            float2 wv = ((const float2*)W)[(k4 * 4 + kk) * 32 + t];
            wp[kk] = pack2(wv.x, wv.y);
        }
#pragma unroll
        for (int m = 0; m < 8; m++) {
            float4 xv = xs[warp * 8 + m][k4];
            ffma2(acc[m], pack2(xv.x, xv.x), wp[0]);
            ffma2(acc[m], pack2(xv.y, xv.y), wp[1]);
            ffma2(acc[m], pack2(xv.z, xv.z), wp[2]);
            ffma2(acc[m], pack2(xv.w, xv.w), wp[3]);
        }
    }

    float2 av = ((const float2*)a_src)[t];
    float2 dv = ((const float2*)a_dst)[t];
#pragma unroll
    for (int m = 0; m < 8; m++) {
        int node = blkbase + warp * 8 + m;
        if (node >= n) break;
        float2 p = unpack2(acc[m]);
        *(float2*)&g_h2[node * 64 + t * 2] = p;
        float s = p.x * av.x + p.y * av.y;
        float d = p.x * dv.x + p.y * dv.y;
#pragma unroll
        for (int off = 16; off; off >>= 1) {
            s += __shfl_xor_sync(0xffffffffu, s, off);
            d += __shfl_xor_sync(0xffffffffu, d, off);
        }
        if (t == 0) {
            g_as2[node] = s;
            g_ad2[node] = d;
        }
    }
}

// ---------------- layer 2 aggregation (gather, warp per node) ----------------
__global__ void k_agg2(const float* __restrict__ b2, int n) {
    int node = (int)((blockIdx.x * (unsigned)blockDim.x + threadIdx.x) >> 5);
    int lane = threadIdx.x & 31;
    if (node >= n) return;

    float ad = __ldg(&g_ad2[node]);
    float v = __ldg(&g_as2[node]) + ad;
    float w = __expf(v > 0.f ? v : 0.2f * v);
    float den = w;
    float2 hv = *(const float2*)&g_h2[node * 64 + lane * 2];
    float2 acc = make_float2(hv.x * w, hv.y * w);

    int rs = g_rowp[node], re = g_rowp[node + 1];
    for (int jb = rs; jb < re; jb += 32) {
        int cnt = re - jb; if (cnt > 32) cnt = 32;
        int cl = (jb + lane < re) ? __ldg(&g_col[jb + lane]) : 0;
        for (int u = 0; u < cnt; u++) {
            int src = __shfl_sync(0xffffffffu, cl, u);
            float vv = __ldg(&g_as2[src]) + ad;
            float ww = __expf(vv > 0.f ? vv : 0.2f * vv);
            den += ww;
            float2 h = *(const float2*)&g_h2[src * 64 + lane * 2];
            acc.x += h.x * ww;
            acc.y += h.y * ww;
        }
    }

    float inv = 1.f / (den + 1e-16f);
    float2 b = ((const float2*)b2)[lane];
    float2 o;
    o.x = acc.x * inv + b.x;
    o.y = acc.y * inv + b.y;
    o.x = o.x > 0.f ? o.x : expm1f(o.x);
    o.y = o.y > 0.f ? o.y : expm1f(o.y);
    *(float2*)&g_o2[node * 64 + lane * 2] = o;
}

// ---------------- MLP: out = relu(o2@pw1+pb1)@pw2+pb2 ----------------
// 256 threads, 16 nodes per block; thread handles 4 nodes x 1 col. f32x2 FMA.
__global__ void k_mlp(const float* __restrict__ pw1, const float* __restrict__ pb1,
                      const float* __restrict__ pw2, const float* __restrict__ pb2,
                      float* __restrict__ out, int n) {
    __shared__ float w1s[64 * 64];
    __shared__ float w2s[64 * 64];
    __shared__ float vs[16][64];
    __shared__ float ts[16][64];
    int tid = threadIdx.x;
    for (int i = tid; i < 4096; i += 256) {
        w1s[i] = pw1[i];
        w2s[i] = pw2[i];
    }
    int ms = tid >> 6, j = tid & 63;
    int base = blockIdx.x * 16;
#pragma unroll
    for (int i = 0; i < 4; i++) {
        int nl = ms * 4 + i;
        int node = base + nl;
        vs[nl][j] = (node < n) ? g_o2[node * 64 + j] : 0.f;
    }
    __syncthreads();

    {
        float bv = pb1[j];
        ull acc[4];
#pragma unroll
        for (int i = 0; i < 4; i++) acc[i] = pack2(bv, 0.f);
#pragma unroll 8
        for (int c = 0; c < 64; c += 2) {
            ull wp = pack2(w1s[c * 64 + j], w1s[(c + 1) * 64 + j]);
#pragma unroll
            for (int i = 0; i < 4; i++) {
                int nl = ms * 4 + i;
                float2 xv = *(const float2*)&vs[nl][c];
                ffma2(acc[i], pack2(xv.x, xv.y), wp);
            }
        }
#pragma unroll
        for (int i = 0; i < 4; i++) {
            float2 p = unpack2(acc[i]);
            ts[ms * 4 + i][j] = fmaxf(p.x + p.y, 0.f);
        }
    }
    __syncthreads();

    {
        float bv = pb2[j];
        ull acc[4];
#pragma unroll
        for (int i = 0; i < 4; i++) acc[i] = pack2(bv, 0.f);
#pragma unroll 8
        for (int c = 0; c < 64; c += 2) {
            ull wp = pack2(w2s[c * 64 + j], w2s[(c + 1) * 64 + j]);
#pragma unroll
            for (int i = 0; i < 4; i++) {
                int nl = ms * 4 + i;
                float2 xv = *(const float2*)&ts[nl][c];
                ffma2(acc[i], pack2(xv.x, xv.y), wp);
            }
        }
#pragma unroll
        for (int i = 0; i < 4; i++) {
            int node = base + ms * 4 + i;
            if (node < n) {
                float2 p = unpack2(acc[i]);
                out[node * 64 + j] = p.x + p.y;
            }
        }
    }
}

// ---------------- launch ----------------
extern "C" void kernel_launch(void* const* d_in, const int* in_sizes, int n_in,
                              void* d_out, int out_size) {
    const float* x        = (const float*)d_in[0];
    const int* ei         = (const int*)d_in[1];   // JAX x64 disabled -> int32
    const float* W1       = (const float*)d_in[2];
    const float* a_src1   = (const float*)d_in[3];
    const float* a_dst1   = (const float*)d_in[4];
    const float* b1       = (const float*)d_in[5];
    const float* W2       = (const float*)d_in[6];
    const float* a_src2   = (const float*)d_in[7];
    const float* a_dst2   = (const float*)d_in[8];
    const float* b2       = (const float*)d_in[9];
    const float* pw1      = (const float*)d_in[10];
    const float* pb1      = (const float*)d_in[11];
    const float* pw2      = (const float*)d_in[12];
    const float* pb2      = (const float*)d_in[13];
    float* out = (float*)d_out;

    int n = in_sizes[0] / 128;   // 50000
    int e = in_sizes[1] / 2;     // 800000

    void *p_deg, *p_cnt;
    cudaGetSymbolAddress(&p_deg, g_deg);
    cudaGetSymbolAddress(&p_cnt, g_cnt);

    // Forked capture: CSR build runs concurrently with gemm1.
    cudaStream_t s2 = 0;
    cudaEvent_t ev0 = 0, ev1 = 0;
    bool forked = (cudaStreamCreateWithFlags(&s2, cudaStreamNonBlocking) == cudaSuccess)
               && (cudaEventCreateWithFlags(&ev0, cudaEventDisableTiming) == cudaSuccess)
               && (cudaEventCreateWithFlags(&ev1, cudaEventDisableTiming) == cudaSuccess);

    if (forked) {
        cudaEventRecord(ev0, 0);
        cudaStreamWaitEvent(s2, ev0, 0);
        cudaMemsetAsync(p_deg, 0, (size_t)n * sizeof(int), s2);
        cudaMemsetAsync(p_cnt, 0, (size_t)n * sizeof(int), s2);
        k_deg<<<(e + 255) / 256, 256, 0, s2>>>(ei, e);
        k_scan<<<1, 1024, 0, s2>>>(n);
        k_fill<<<(e + 255) / 256, 256, 0, s2>>>(ei, e);
        cudaEventRecord(ev1, s2);

        k_gemm1<<<(n + 63) / 64, 256>>>(x, W1, a_src1, a_dst1, n);
        cudaStreamWaitEvent(0, ev1, 0);   // join: agg1 needs CSR + gemm1
    } else {
        cudaMemsetAsync(p_deg, 0, (size_t)n * sizeof(int));
        cudaMemsetAsync(p_cnt, 0, (size_t)n * sizeof(int));
        k_deg<<<(e + 255) / 256, 256>>>(ei, e);
        k_scan<<<1, 1024>>>(n);
        k_fill<<<(e + 255) / 256, 256>>>(ei, e);
        k_gemm1<<<(n + 63) / 64, 256>>>(x, W1, a_src1, a_dst1, n);
    }

    k_agg1<<<(n * 32 + 255) / 256, 256>>>(b1, n);
    k_gemm2<<<(n + 63) / 64, 256>>>(W2, a_src2, a_dst2, n);
    k_agg2<<<(n * 32 + 255) / 256, 256>>>(b2, n);
    k_mlp<<<(n + 15) / 16, 256>>>(pw1, pb1, pw2, pb2, out, n);
}

// round 15
// speedup vs baseline: 1.1715x; 1.1715x over previous
#include <cuda_runtime.h>
#include <math.h>

#define NN 50000
#define EE 800000

typedef unsigned long long ull;

__device__ __forceinline__ ull pack2(float lo, float hi) {
    ull r;
    asm("mov.b64 %0, {%1,%2};" : "=l"(r) : "f"(lo), "f"(hi));
    return r;
}
__device__ __forceinline__ float2 unpack2(ull v) {
    float2 r;
    asm("mov.b64 {%0,%1}, %2;" : "=f"(r.x), "=f"(r.y) : "l"(v));
    return r;
}
__device__ __forceinline__ void ffma2(ull& acc, ull a, ull b) {
    asm("fma.rn.f32x2 %0, %1, %2, %3;" : "=l"(acc) : "l"(a), "l"(b), "l"(acc));
}

// ---------------- scratch (device globals; no allocation) ----------------
__device__ float g_h1[NN * 128];     // h1 = x@W1 (pre-aggregation)
__device__ float g_as1[NN * 4];
__device__ float g_ad1[NN * 4];
__device__ float g_o1[NN * 128];     // ELU(aggregated layer-1 output)
__device__ float g_h2[NN * 64];      // h2 = o1@W2 (pre-aggregation)
__device__ float g_as2[NN];
__device__ float g_ad2[NN];
__device__ float g_o2[NN * 64];      // ELU(aggregated layer-2 output)
__device__ int   g_deg[NN];
__device__ int   g_cnt[NN];          // running cursor (init = rowp by k_scan)
__device__ int   g_rowp[NN + 1];
__device__ int   g_col[EE];

// ---------------- CSR build ----------------
__global__ void k_deg(const int* __restrict__ ei, int e) {
    int i = blockIdx.x * blockDim.x + threadIdx.x;
    if (i < e) atomicAdd(&g_deg[ei[e + i]], 1);
}

// one block, 1024 threads: serial chunk sums + block scan + serial writeback.
// Also writes the exclusive prefix into g_cnt (cursor for k_fill).
__global__ void k_scan(int n) {
    __shared__ int part[1024];
    int tid = threadIdx.x;
    int C = (n + 1023) / 1024;
    int base = tid * C;
    int sum = 0;
    for (int i = 0; i < C; i++) {
        int idx = base + i;
        if (idx < n) sum += g_deg[idx];
    }
    part[tid] = sum;
    __syncthreads();
    for (int off = 1; off < 1024; off <<= 1) {
        int t = (tid >= off) ? part[tid - off] : 0;
        __syncthreads();
        part[tid] += t;
        __syncthreads();
    }
    int run = part[tid] - sum;   // exclusive
    for (int i = 0; i < C; i++) {
        int idx = base + i;
        if (idx < n) {
            g_rowp[idx] = run;
            g_cnt[idx] = run;
            run += g_deg[idx];
        }
    }
    if (tid == 1023) g_rowp[n] = part[1023];
}

__global__ void k_fill(const int* __restrict__ ei, int e) {
    int i = blockIdx.x * blockDim.x + threadIdx.x;
    if (i < e) {
        int src = ei[i];
        int dst = ei[e + i];
        int pos = atomicAdd(&g_cnt[dst], 1);
        g_col[pos] = src;
    }
}

// ---------------- layer 1 GEMM: h1 = x @ W1, alpha reductions ----------------
// 128 threads = 4 warps; each warp owns an 8-node tile, 4 cols per lane.
__global__ void __launch_bounds__(128) k_gemm1(
        const float* __restrict__ x, const float* __restrict__ W,
        const float* __restrict__ a_src, const float* __restrict__ a_dst,
        int n) {
    __shared__ float4 xs[32][32];
    int tid = threadIdx.x;
    int warp = tid >> 5;                // warp = 8-node tile (0..3)
    int t = tid & 31;                   // lane = column group (cols 4t..4t+3)
    int blkbase = blockIdx.x * 32;

    for (int i = tid; i < 32 * 32; i += 128) {
        int m = i >> 5, k4 = i & 31;
        int node = blkbase + m;
        xs[m][k4] = (node < n) ? ((const float4*)x)[node * 32 + k4]
                               : make_float4(0.f, 0.f, 0.f, 0.f);
    }
    __syncthreads();

    ull accA[8], accB[8];               // (4t,4t+1) and (4t+2,4t+3)
#pragma unroll
    for (int m = 0; m < 8; m++) { accA[m] = 0ull; accB[m] = 0ull; }

#pragma unroll 2
    for (int k4 = 0; k4 < 32; k4++) {
        ull wpA[4], wpB[4];
#pragma unroll
        for (int kk = 0; kk < 4; kk++) {
            float4 wv = ((const float4*)W)[(k4 * 4 + kk) * 32 + t];
            wpA[kk] = pack2(wv.x, wv.y);
            wpB[kk] = pack2(wv.z, wv.w);
        }
#pragma unroll
        for (int m = 0; m < 8; m++) {
            float4 xv = xs[warp * 8 + m][k4];
            ull xx = pack2(xv.x, xv.x);
            ffma2(accA[m], xx, wpA[0]); ffma2(accB[m], xx, wpB[0]);
            xx = pack2(xv.y, xv.y);
            ffma2(accA[m], xx, wpA[1]); ffma2(accB[m], xx, wpB[1]);
            xx = pack2(xv.z, xv.z);
            ffma2(accA[m], xx, wpA[2]); ffma2(accB[m], xx, wpB[2]);
            xx = pack2(xv.w, xv.w);
            ffma2(accA[m], xx, wpA[3]); ffma2(accB[m], xx, wpB[3]);
        }
    }

    int head = t >> 3;                  // cols 4t..4t+3 lie within head t/8
    float4 av = ((const float4*)a_src)[t];
    float4 dv = ((const float4*)a_dst)[t];
#pragma unroll
    for (int m = 0; m < 8; m++) {
        int node = blkbase + warp * 8 + m;
        if (node >= n) break;
        float2 pa = unpack2(accA[m]);
        float2 pb = unpack2(accB[m]);
        float4 o = make_float4(pa.x, pa.y, pb.x, pb.y);
        *(float4*)&g_h1[node * 128 + t * 4] = o;
        float s = o.x * av.x + o.y * av.y + o.z * av.z + o.w * av.w;
        float d = o.x * dv.x + o.y * dv.y + o.z * dv.z + o.w * dv.w;
#pragma unroll
        for (int off = 4; off; off >>= 1) {
            s += __shfl_xor_sync(0xffffffffu, s, off);
            d += __shfl_xor_sync(0xffffffffu, d, off);
        }
        if ((t & 7) == 0) {
            g_as1[node * 4 + head] = s;
            g_ad1[node * 4 + head] = d;
        }
    }
}

// ---------------- layer 1 aggregation (gather, warp per node) ----------------
// batched col loads (one coalesced LDG per 32 edges), single accumulator.
__global__ void k_agg1(const float* __restrict__ b1, int n) {
    int node = (int)((blockIdx.x * (unsigned)blockDim.x + threadIdx.x) >> 5);
    int lane = threadIdx.x & 31;
    if (node >= n) return;
    int head = lane >> 3;

    float ad = __ldg(&g_ad1[node * 4 + head]);
    float v = __ldg(&g_as1[node * 4 + head]) + ad;   // self loop
    float w = __expf(v > 0.f ? v : 0.2f * v);
    float den = w;
    float4 hv = *(const float4*)&g_h1[node * 128 + lane * 4];
    float4 acc = make_float4(hv.x * w, hv.y * w, hv.z * w, hv.w * w);

    int rs = g_rowp[node], re = g_rowp[node + 1];
    for (int jb = rs; jb < re; jb += 32) {
        int cnt = re - jb; if (cnt > 32) cnt = 32;
        int cl = (jb + lane < re) ? __ldg(&g_col[jb + lane]) : 0;
        for (int u = 0; u < cnt; u++) {
            int src = __shfl_sync(0xffffffffu, cl, u);
            float vv = __ldg(&g_as1[src * 4 + head]) + ad;
            float ww = __expf(vv > 0.f ? vv : 0.2f * vv);
            den += ww;
            float4 h = *(const float4*)&g_h1[src * 128 + lane * 4];
            acc.x += h.x * ww;
            acc.y += h.y * ww;
            acc.z += h.z * ww;
            acc.w += h.w * ww;
        }
    }

    float inv = 1.f / (den + 1e-16f);
    float4 b = ((const float4*)b1)[lane];
    float4 o;
    o.x = acc.x * inv + b.x;
    o.y = acc.y * inv + b.y;
    o.z = acc.z * inv + b.z;
    o.w = acc.w * inv + b.w;
    o.x = o.x > 0.f ? o.x : expm1f(o.x);
    o.y = o.y > 0.f ? o.y : expm1f(o.y);
    o.z = o.z > 0.f ? o.z : expm1f(o.z);
    o.w = o.w > 0.f ? o.w : expm1f(o.w);
    *(float4*)&g_o1[node * 128 + lane * 4] = o;
}

// ---------------- layer 2 GEMM: h2 = o1 @ W2, scalar alphas ----------------
// 128 threads = 4 warps; each warp owns an 8-node tile, 2 cols per lane.
__global__ void __launch_bounds__(128) k_gemm2(
        const float* __restrict__ W, const float* __restrict__ a_src,
        const float* __restrict__ a_dst, int n) {
    __shared__ float4 xs[32][32];
    int tid = threadIdx.x;
    int warp = tid >> 5;
    int t = tid & 31;                   // cols 2t, 2t+1
    int blkbase = blockIdx.x * 32;

    for (int i = tid; i < 32 * 32; i += 128) {
        int m = i >> 5, k4 = i & 31;
        int node = blkbase + m;
        xs[m][k4] = (node < n) ? ((const float4*)g_o1)[node * 32 + k4]
                               : make_float4(0.f, 0.f, 0.f, 0.f);
    }
    __syncthreads();

    ull acc[8];
#pragma unroll
    for (int m = 0; m < 8; m++) acc[m] = 0ull;

#pragma unroll 2
    for (int k4 = 0; k4 < 32; k4++) {
        ull wp[4];
#pragma unroll
        for (int kk = 0; kk < 4; kk++) {
            float2 wv = ((const float2*)W)[(k4 * 4 + kk) * 32 + t];
            wp[kk] = pack2(wv.x, wv.y);
        }
#pragma unroll
        for (int m = 0; m < 8; m++) {
            float4 xv = xs[warp * 8 + m][k4];
            ffma2(acc[m], pack2(xv.x, xv.x), wp[0]);
            ffma2(acc[m], pack2(xv.y, xv.y), wp[1]);
            ffma2(acc[m], pack2(xv.z, xv.z), wp[2]);
            ffma2(acc[m], pack2(xv.w, xv.w), wp[3]);
        }
    }

    float2 av = ((const float2*)a_src)[t];
    float2 dv = ((const float2*)a_dst)[t];
#pragma unroll
    for (int m = 0; m < 8; m++) {
        int node = blkbase + warp * 8 + m;
        if (node >= n) break;
        float2 p = unpack2(acc[m]);
        *(float2*)&g_h2[node * 64 + t * 2] = p;
        float s = p.x * av.x + p.y * av.y;
        float d = p.x * dv.x + p.y * dv.y;
#pragma unroll
        for (int off = 16; off; off >>= 1) {
            s += __shfl_xor_sync(0xffffffffu, s, off);
            d += __shfl_xor_sync(0xffffffffu, d, off);
        }
        if (t == 0) {
            g_as2[node] = s;
            g_ad2[node] = d;
        }
    }
}

// ---------------- layer 2 aggregation (gather, warp per node) ----------------
__global__ void k_agg2(const float* __restrict__ b2, int n) {
    int node = (int)((blockIdx.x * (unsigned)blockDim.x + threadIdx.x) >> 5);
    int lane = threadIdx.x & 31;
    if (node >= n) return;

    float ad = __ldg(&g_ad2[node]);
    float v = __ldg(&g_as2[node]) + ad;
    float w = __expf(v > 0.f ? v : 0.2f * v);
    float den = w;
    float2 hv = *(const float2*)&g_h2[node * 64 + lane * 2];
    float2 acc = make_float2(hv.x * w, hv.y * w);

    int rs = g_rowp[node], re = g_rowp[node + 1];
    for (int jb = rs; jb < re; jb += 32) {
        int cnt = re - jb; if (cnt > 32) cnt = 32;
        int cl = (jb + lane < re) ? __ldg(&g_col[jb + lane]) : 0;
        for (int u = 0; u < cnt; u++) {
            int src = __shfl_sync(0xffffffffu, cl, u);
            float vv = __ldg(&g_as2[src]) + ad;
            float ww = __expf(vv > 0.f ? vv : 0.2f * vv);
            den += ww;
            float2 h = *(const float2*)&g_h2[src * 64 + lane * 2];
            acc.x += h.x * ww;
            acc.y += h.y * ww;
        }
    }

    float inv = 1.f / (den + 1e-16f);
    float2 b = ((const float2*)b2)[lane];
    float2 o;
    o.x = acc.x * inv + b.x;
    o.y = acc.y * inv + b.y;
    o.x = o.x > 0.f ? o.x : expm1f(o.x);
    o.y = o.y > 0.f ? o.y : expm1f(o.y);
    *(float2*)&g_o2[node * 64 + lane * 2] = o;
}

// ---------------- MLP: out = relu(o2@pw1+pb1)@pw2+pb2 ----------------
// 256 threads, 32 nodes per block; each 64-thread group handles 8 nodes.
__global__ void k_mlp(const float* __restrict__ pw1, const float* __restrict__ pb1,
                      const float* __restrict__ pw2, const float* __restrict__ pb2,
                      float* __restrict__ out, int n) {
    __shared__ float w1s[64 * 64];
    __shared__ float w2s[64 * 64];
    __shared__ float vs[32][64];
    __shared__ float ts[32][64];
    int tid = threadIdx.x;
    for (int i = tid; i < 4096; i += 256) {
        w1s[i] = pw1[i];
        w2s[i] = pw2[i];
    }
    int ms = tid >> 6, j = tid & 63;
    int base = blockIdx.x * 32;
#pragma unroll
    for (int i = 0; i < 8; i++) {
        int nl = ms * 8 + i;
        int node = base + nl;
        vs[nl][j] = (node < n) ? g_o2[node * 64 + j] : 0.f;
    }
    __syncthreads();

    {
        float bv = pb1[j];
        ull acc[8];
#pragma unroll
        for (int i = 0; i < 8; i++) acc[i] = pack2(bv, 0.f);
#pragma unroll 8
        for (int c = 0; c < 64; c += 2) {
            ull wp = pack2(w1s[c * 64 + j], w1s[(c + 1) * 64 + j]);
#pragma unroll
            for (int i = 0; i < 8; i++) {
                int nl = ms * 8 + i;
                float2 xv = *(const float2*)&vs[nl][c];
                ffma2(acc[i], pack2(xv.x, xv.y), wp);
            }
        }
#pragma unroll
        for (int i = 0; i < 8; i++) {
            float2 p = unpack2(acc[i]);
            ts[ms * 8 + i][j] = fmaxf(p.x + p.y, 0.f);
        }
    }
    __syncthreads();

    {
        float bv = pb2[j];
        ull acc[8];
#pragma unroll
        for (int i = 0; i < 8; i++) acc[i] = pack2(bv, 0.f);
#pragma unroll 8
        for (int c = 0; c < 64; c += 2) {
            ull wp = pack2(w2s[c * 64 + j], w2s[(c + 1) * 64 + j]);
#pragma unroll
            for (int i = 0; i < 8; i++) {
                int nl = ms * 8 + i;
                float2 xv = *(const float2*)&ts[nl][c];
                ffma2(acc[i], pack2(xv.x, xv.y), wp);
            }
        }
#pragma unroll
        for (int i = 0; i < 8; i++) {
            int node = base + ms * 8 + i;
            if (node < n) {
                float2 p = unpack2(acc[i]);
                out[node * 64 + j] = p.x + p.y;
            }
        }
    }
}

// ---------------- launch ----------------
extern "C" void kernel_launch(void* const* d_in, const int* in_sizes, int n_in,
                              void* d_out, int out_size) {
    const float* x        = (const float*)d_in[0];
    const int* ei         = (const int*)d_in[1];   // JAX x64 disabled -> int32
    const float* W1       = (const float*)d_in[2];
    const float* a_src1   = (const float*)d_in[3];
    const float* a_dst1   = (const float*)d_in[4];
    const float* b1       = (const float*)d_in[5];
    const float* W2       = (const float*)d_in[6];
    const float* a_src2   = (const float*)d_in[7];
    const float* a_dst2   = (const float*)d_in[8];
    const float* b2       = (const float*)d_in[9];
    const float* pw1      = (const float*)d_in[10];
    const float* pb1      = (const float*)d_in[11];
    const float* pw2      = (const float*)d_in[12];
    const float* pb2      = (const float*)d_in[13];
    float* out = (float*)d_out;

    int n = in_sizes[0] / 128;   // 50000
    int e = in_sizes[1] / 2;     // 800000

    void *p_deg;
    cudaGetSymbolAddress(&p_deg, g_deg);

    // Forked capture: deg runs on main first (short), then scan+fill hide
    // under gemm1 on the side stream.
    cudaStream_t s2 = 0;
    cudaEvent_t ev0 = 0, ev1 = 0;
    bool forked = (cudaStreamCreateWithFlags(&s2, cudaStreamNonBlocking) == cudaSuccess)
               && (cudaEventCreateWithFlags(&ev0, cudaEventDisableTiming) == cudaSuccess)
               && (cudaEventCreateWithFlags(&ev1, cudaEventDisableTiming) == cudaSuccess);

    if (forked) {
        cudaMemsetAsync(p_deg, 0, (size_t)n * sizeof(int));
        k_deg<<<(e + 255) / 256, 256>>>(ei, e);
        cudaEventRecord(ev0, 0);
        cudaStreamWaitEvent(s2, ev0, 0);
        k_scan<<<1, 1024, 0, s2>>>(n);
        k_fill<<<(e + 255) / 256, 256, 0, s2>>>(ei, e);
        cudaEventRecord(ev1, s2);

        k_gemm1<<<(n + 31) / 32, 128>>>(x, W1, a_src1, a_dst1, n);
        cudaStreamWaitEvent(0, ev1, 0);   // join: agg1 needs CSR + gemm1
    } else {
        cudaMemsetAsync(p_deg, 0, (size_t)n * sizeof(int));
        k_deg<<<(e + 255) / 256, 256>>>(ei, e);
        k_scan<<<1, 1024>>>(n);
        k_fill<<<(e + 255) / 256, 256>>>(ei, e);
        k_gemm1<<<(n + 31) / 32, 128>>>(x, W1, a_src1, a_dst1, n);
    }

    k_agg1<<<(n * 32 + 255) / 256, 256>>>(b1, n);
    k_gemm2<<<(n + 31) / 32, 128>>>(W2, a_src2, a_dst2, n);
    k_agg2<<<(n * 32 + 255) / 256, 256>>>(b2, n);
    k_mlp<<<(n + 31) / 32, 256>>>(pw1, pb1, pw2, pb2, out, n);
}